// round 1
// baseline (speedup 1.0000x reference)
#include <cuda_runtime.h>
#include <math.h>

#define NN  50000
#define NE  800000
#define H   96
#define IND 256

// Scratch (allocation-free rule: __device__ globals). 4 x 19.2 MB = 76.8 MB.
__device__ float g_h[(size_t)NN * H];
__device__ float g_p[(size_t)NN * H];
__device__ float g_q[(size_t)NN * H];
__device__ float g_z[(size_t)NN * H];

// ---------------------------------------------------------------------------
// zero g_z (float4 grid-stride)
// ---------------------------------------------------------------------------
__global__ void zero_kernel(float* __restrict__ p, int n4) {
    int i = blockIdx.x * blockDim.x + threadIdx.x;
    if (i < n4) ((float4*)p)[i] = make_float4(0.f, 0.f, 0.f, 0.f);
}

// ---------------------------------------------------------------------------
// C[m, 0..95] = sum_k A[m,k] * W[n*ldw + koff + k] (+ bias[n])
// BM=64, BN=96, BK=16, TM=8, TN=3, 256 threads. Requires K % 16 == 0.
// ---------------------------------------------------------------------------
__global__ void gemm96(const float* __restrict__ A,
                       const float* __restrict__ W,
                       const float* __restrict__ bias,
                       float* __restrict__ C,
                       int M, int K, int ldw, int koff)
{
    __shared__ float As[16][68];   // [k][m], padded to kill store conflicts
    __shared__ float Bs[16][96];   // [k][n]

    const int tid = threadIdx.x;
    const int tx  = tid & 31;      // n-group: cols tx, tx+32, tx+64
    const int ty  = tid >> 5;      // m-group: rows ty*8 .. ty*8+7
    const int m0  = blockIdx.x * 64;

    float acc[8][3];
#pragma unroll
    for (int i = 0; i < 8; ++i)
#pragma unroll
        for (int j = 0; j < 3; ++j) acc[i][j] = 0.f;

    for (int k0 = 0; k0 < K; k0 += 16) {
        // --- load A tile 64x16 (float4 per thread), transpose into As ---
        {
            int row  = tid >> 2;           // 0..63
            int kseg = (tid & 3) << 2;     // 0,4,8,12
            float4 v = make_float4(0.f, 0.f, 0.f, 0.f);
            int gm = m0 + row;
            if (gm < M)
                v = *(const float4*)(A + (size_t)gm * K + k0 + kseg);
            As[kseg + 0][row] = v.x;
            As[kseg + 1][row] = v.y;
            As[kseg + 2][row] = v.z;
            As[kseg + 3][row] = v.w;
        }
        // --- load W tile 96x16 ---
        for (int i = tid; i < 96 * 16; i += 256) {
            int n = i >> 4, k = i & 15;
            Bs[k][n] = W[(size_t)n * ldw + koff + k0 + k];
        }
        __syncthreads();

#pragma unroll
        for (int k = 0; k < 16; ++k) {
            float b0 = Bs[k][tx], b1 = Bs[k][tx + 32], b2 = Bs[k][tx + 64];
#pragma unroll
            for (int i = 0; i < 8; ++i) {
                float a = As[k][ty * 8 + i];
                acc[i][0] += a * b0;
                acc[i][1] += a * b1;
                acc[i][2] += a * b2;
            }
        }
        __syncthreads();
    }

    float bb0 = bias ? bias[tx]      : 0.f;
    float bb1 = bias ? bias[tx + 32] : 0.f;
    float bb2 = bias ? bias[tx + 64] : 0.f;

#pragma unroll
    for (int i = 0; i < 8; ++i) {
        int m = m0 + ty * 8 + i;
        if (m < M) {
            float* cr = C + (size_t)m * 96;
            cr[tx]      = acc[i][0] + bb0;
            cr[tx + 32] = acc[i][1] + bb1;
            cr[tx + 64] = acc[i][2] + bb2;
        }
    }
}

// ---------------------------------------------------------------------------
// Edge kernel: one warp per edge, lanes 0..23 each own one float4 (4 cols).
//   a = tanh((p[dst] + q[src] + b_gate) / sqrt(192))      -> written to out
//   msg = h[src] * a * (d[dst]*d[src])                    -> red.v4 into g_z
// p,q,h,z all L2-resident (76.8 MB total).
// ---------------------------------------------------------------------------
__global__ void edge_kernel(const int*   __restrict__ src,
                            const int*   __restrict__ dst,
                            const float* __restrict__ d,
                            const float* __restrict__ bgate,
                            float* __restrict__ a_out)
{
    int e = blockIdx.x * 8 + (threadIdx.x >> 5);
    if (e >= NE) return;
    int lane = threadIdx.x & 31;

    int s = __ldg(src + e);
    int t = __ldg(dst + e);
    float ed = __ldg(d + t) * __ldg(d + s);

    if (lane >= 24) return;

    const float4 pv = ((const float4*)(g_p + (size_t)t * H))[lane];
    const float4 qv = ((const float4*)(g_q + (size_t)s * H))[lane];
    const float4 hv = ((const float4*)(g_h + (size_t)s * H))[lane];
    const float4 bv = ((const float4*)bgate)[lane];

    const float ic = 0.07216878364870322f;   // 1/sqrt(192)
    float4 av;
    av.x = tanhf((pv.x + qv.x + bv.x) * ic);
    av.y = tanhf((pv.y + qv.y + bv.y) * ic);
    av.z = tanhf((pv.z + qv.z + bv.z) * ic);
    av.w = tanhf((pv.w + qv.w + bv.w) * ic);

    ((float4*)a_out)[(size_t)e * 24 + lane] = av;

    float4 mv = make_float4(hv.x * av.x * ed, hv.y * av.y * ed,
                            hv.z * av.z * ed, hv.w * av.w * ed);

    float* zp = g_z + (size_t)t * H + lane * 4;
    asm volatile("red.global.add.v4.f32 [%0], {%1, %2, %3, %4};"
                 :: "l"(zp), "f"(mv.x), "f"(mv.y), "f"(mv.z), "f"(mv.w)
                 : "memory");
}

// ---------------------------------------------------------------------------
// Classifier: one warp per node. y = z@W_clf^T + b_clf, then log_softmax(2).
// ---------------------------------------------------------------------------
__global__ void clf_kernel(const float* __restrict__ Wc,
                           const float* __restrict__ bc,
                           float* __restrict__ out)
{
    int n = blockIdx.x * 8 + (threadIdx.x >> 5);
    if (n >= NN) return;
    int lane = threadIdx.x & 31;

    const float* zr = g_z + (size_t)n * H;
    float s0 = 0.f, s1 = 0.f;
#pragma unroll
    for (int j = 0; j < 3; ++j) {
        float zv = zr[lane + 32 * j];
        s0 += zv * __ldg(Wc + lane + 32 * j);
        s1 += zv * __ldg(Wc + 96 + lane + 32 * j);
    }
#pragma unroll
    for (int o = 16; o; o >>= 1) {
        s0 += __shfl_xor_sync(0xffffffffu, s0, o);
        s1 += __shfl_xor_sync(0xffffffffu, s1, o);
    }
    if (lane == 0) {
        float y0 = s0 + bc[0];
        float y1 = s1 + bc[1];
        float m  = fmaxf(y0, y1);
        float lse = m + logf(expf(y0 - m) + expf(y1 - m));
        out[2 * n]     = y0 - lse;
        out[2 * n + 1] = y1 - lse;
    }
}

// ---------------------------------------------------------------------------
extern "C" void kernel_launch(void* const* d_in, const int* in_sizes, int n_in,
                              void* d_out, int out_size)
{
    const float* x      = (const float*)d_in[0];
    const float* d      = (const float*)d_in[1];
    const int*   src    = (const int*)  d_in[2];
    const int*   dst    = (const int*)  d_in[3];
    const float* W_in   = (const float*)d_in[4];
    const float* b_in   = (const float*)d_in[5];
    const float* W_gate = (const float*)d_in[6];
    const float* b_gate = (const float*)d_in[7];
    const float* W_clf  = (const float*)d_in[8];
    const float* b_clf  = (const float*)d_in[9];
    float* out = (float*)d_out;

    float *hp, *pp, *qp, *zp;
    cudaGetSymbolAddress((void**)&hp, g_h);
    cudaGetSymbolAddress((void**)&pp, g_p);
    cudaGetSymbolAddress((void**)&qp, g_q);
    cudaGetSymbolAddress((void**)&zp, g_z);

    // z accumulator must start at zero every replay
    zero_kernel<<<(NN * H / 4 + 255) / 256, 256>>>(zp, NN * H / 4);

    // h = x @ W_in^T + b_in
    gemm96<<<(NN + 63) / 64, 256>>>(x, W_in, b_in, hp, NN, IND, IND, 0);
    // p = h @ Wg[:, :96]^T   (dst half)
    gemm96<<<(NN + 63) / 64, 256>>>(hp, W_gate, nullptr, pp, NN, H, 2 * H, 0);
    // q = h @ Wg[:, 96:]^T   (src half)
    gemm96<<<(NN + 63) / 64, 256>>>(hp, W_gate, nullptr, qp, NN, H, 2 * H, H);

    // a + scatter z   (output tuple order: z [50000,2] first, then a [800000,96])
    edge_kernel<<<(NE + 7) / 8, 256>>>(src, dst, d, b_gate, out + 2 * NN);

    // z-part of output
    clf_kernel<<<(NN + 7) / 8, 256>>>(W_clf, b_clf, out);
}